// round 1
// baseline (speedup 1.0000x reference)
#include <cuda_runtime.h>
#include <math.h>

#define N_NODES 50000
#define N_EDGES 800000
#define HID 64

// ---------------- scratch (device globals; no allocation allowed) ----------------
__device__ float g_h[N_NODES*HID];        // current layer input
__device__ float g_feat[N_NODES*HID];     // h @ W_gat[l]
__device__ float g_agg[N_NODES*HID];      // aggregation accumulator
__device__ float g_fcat[N_NODES*4*HID];   // concat buffer [N,256]
__device__ float g_el[N_NODES];
__device__ float g_er[N_NODES];
__device__ unsigned int g_nmaxk[N_NODES]; // monotone-encoded segment max
__device__ float g_nsum[N_NODES];
__device__ float g_escore[N_EDGES];
__device__ float g_aexp[N_EDGES];
__device__ unsigned char g_mask[N_EDGES];

// monotone order-preserving float<->uint encoding (for atomicMax on floats incl. negatives)
__device__ __forceinline__ unsigned fenc(float x){
  unsigned u = __float_as_uint(x);
  return (u & 0x80000000u) ? ~u : (u | 0x80000000u);
}
__device__ __forceinline__ float fdec(unsigned u){
  return __uint_as_float((u & 0x80000000u) ? (u ^ 0x80000000u) : ~u);
}
// fenc(-inf) = ~0xFF800000 = 0x007FFFFF
#define ENC_NEG_INF 0x007FFFFFu

// ---------------- GEMM: out[row,0:64] = act(A[row,:K] @ W[K,64]) ----------------
// one warp per row; W staged in smem; shuffle-broadcast of A row values.
template<int K, bool TANH, bool ELER>
__global__ void gemm_k(const float* __restrict__ A, const float* __restrict__ W,
                       const float* __restrict__ al, const float* __restrict__ ar,
                       float* __restrict__ out, float* __restrict__ el, float* __restrict__ er,
                       int n)
{
  __shared__ float Wsh[K*64];
  int tid = threadIdx.x;
  for (int i = tid; i < K*64; i += blockDim.x) Wsh[i] = W[i];
  __syncthreads();
  int warp = tid >> 5, lane = tid & 31;
  int row = blockIdx.x * 8 + warp;
  if (row >= n) return;
  float acc0 = 0.f, acc1 = 0.f;
  #pragma unroll
  for (int kc = 0; kc < K; kc += 64) {
    float2 hv = *(const float2*)(A + (size_t)row*K + kc + 2*lane);
    #pragma unroll
    for (int kk = 0; kk < 64; ++kk) {
      float hk = __shfl_sync(0xffffffffu, (kk & 1) ? hv.y : hv.x, kk >> 1);
      acc0 = fmaf(hk, Wsh[(kc+kk)*64 + 2*lane],     acc0);
      acc1 = fmaf(hk, Wsh[(kc+kk)*64 + 2*lane + 1], acc1);
    }
  }
  if (TANH) { acc0 = tanhf(acc0); acc1 = tanhf(acc1); }
  out[(size_t)row*64 + 2*lane]     = acc0;
  out[(size_t)row*64 + 2*lane + 1] = acc1;
  if (ELER) {
    float pl = acc0*al[2*lane] + acc1*al[2*lane+1];
    float pr = acc0*ar[2*lane] + acc1*ar[2*lane+1];
    #pragma unroll
    for (int o = 16; o; o >>= 1) {
      pl += __shfl_xor_sync(0xffffffffu, pl, o);
      pr += __shfl_xor_sync(0xffffffffu, pr, o);
    }
    if (lane == 0) { el[row] = pl; er[row] = pr; }
  }
}

// ---------------- per-layer init ----------------
__global__ void init_k(int n){
  int i = blockIdx.x*blockDim.x + threadIdx.x;
  if (i < n*HID) g_agg[i] = 0.f;
  if (i < n) { g_nmaxk[i] = ENC_NEG_INF; g_nsum[i] = 0.f; }
}

// ---------------- edge pass 1: raw score + segment max ----------------
__global__ void edge_max_k(const int* __restrict__ src, const int* __restrict__ dst,
                           int e, int use_mask){
  int i = blockIdx.x*blockDim.x + threadIdx.x;
  if (i >= e) return;
  float v = g_el[src[i]] + g_er[dst[i]];
  v = (v >= 0.f) ? v : 0.2f*v;                       // leaky_relu slope 0.2
  if (use_mask && !g_mask[i]) v = -1e9f;             // pruned edge
  g_escore[i] = v;
  atomicMax(&g_nmaxk[dst[i]], fenc(v));
}

// ---------------- edge pass 2: exp + segment sum ----------------
__global__ void edge_exp_k(const int* __restrict__ dst, int e){
  int i = blockIdx.x*blockDim.x + threadIdx.x;
  if (i >= e) return;
  int d = dst[i];
  float a = expf(g_escore[i] - fdec(g_nmaxk[d]));
  g_aexp[i] = a;
  atomicAdd(&g_nsum[d], a);
}

// ---------------- edge pass 3: normalize + gather/scatter aggregate ----------------
// 16 threads per edge, one float4 each; sm_90+ vector float4 atomicAdd.
__global__ void edge_agg_k(const int* __restrict__ src, const int* __restrict__ dst,
                           int e, int write_mask){
  int idx = blockIdx.x*blockDim.x + threadIdx.x;
  int edge = idx >> 4, c = idx & 15;
  if (edge >= e) return;
  int d = dst[edge];
  float alpha = g_aexp[edge] / fmaxf(g_nsum[d], 1e-9f);
  if (write_mask && c == 0) g_mask[edge] = (alpha >= 0.01f) ? 1 : 0;
  if (alpha != 0.f) {
    int s = src[edge];
    float4 f = *(const float4*)(g_feat + (size_t)s*64 + c*4);
    float4 v = make_float4(f.x*alpha, f.y*alpha, f.z*alpha, f.w*alpha);
    atomicAdd((float4*)(g_agg + (size_t)d*64 + c*4), v);
  }
}

// ---------------- ELU + write into h (next layer input) and fcat slot ----------------
__global__ void elu_k(int n, int slot){
  int j = blockIdx.x*blockDim.x + threadIdx.x;
  if (j >= n*HID) return;
  float v = g_agg[j];
  float o = (v > 0.f) ? v : expm1f(v);
  g_h[j] = o;
  int row = j >> 6, col = j & 63;
  g_fcat[(size_t)row*256 + slot*64 + col] = o;
}

// ---------------- fused MLP head: fcat[N,256] -> 64 -> 64 -> 1 ----------------
__global__ void mlp_k(const float* __restrict__ W0, const float* __restrict__ b0,
                      const float* __restrict__ W1, const float* __restrict__ b1,
                      const float* __restrict__ W2, const float* __restrict__ b2,
                      float* __restrict__ out, int n)
{
  __shared__ float Wsh[64*64];
  int tid = threadIdx.x, warp = tid >> 5, lane = tid & 31;
  int row = blockIdx.x * 8 + warp;
  int r = row < n ? row : (n - 1);     // clamp so all threads reach barriers
  float t0a = 0.f, t0b = 0.f;
  for (int kc = 0; kc < 256; kc += 64) {
    __syncthreads();
    for (int i = tid; i < 64*64; i += blockDim.x) Wsh[i] = W0[kc*64 + i];
    __syncthreads();
    float2 fv = *(const float2*)(g_fcat + (size_t)r*256 + kc + 2*lane);
    #pragma unroll
    for (int kk = 0; kk < 64; ++kk) {
      float fk = __shfl_sync(0xffffffffu, (kk & 1) ? fv.y : fv.x, kk >> 1);
      t0a = fmaf(fk, Wsh[kk*64 + 2*lane],     t0a);
      t0b = fmaf(fk, Wsh[kk*64 + 2*lane + 1], t0b);
    }
  }
  t0a = fmaxf(t0a + b0[2*lane],     0.f);
  t0b = fmaxf(t0b + b0[2*lane + 1], 0.f);
  __syncthreads();
  for (int i = tid; i < 64*64; i += blockDim.x) Wsh[i] = W1[i];
  __syncthreads();
  float t1a = 0.f, t1b = 0.f;
  #pragma unroll
  for (int kk = 0; kk < 64; ++kk) {
    float fk = __shfl_sync(0xffffffffu, (kk & 1) ? t0b : t0a, kk >> 1);
    t1a = fmaf(fk, Wsh[kk*64 + 2*lane],     t1a);
    t1b = fmaf(fk, Wsh[kk*64 + 2*lane + 1], t1b);
  }
  t1a = fmaxf(t1a + b1[2*lane],     0.f);
  t1b = fmaxf(t1b + b1[2*lane + 1], 0.f);
  float s = t1a*W2[2*lane] + t1b*W2[2*lane + 1];
  #pragma unroll
  for (int o = 16; o; o >>= 1) s += __shfl_xor_sync(0xffffffffu, s, o);
  if (lane == 0 && row < n) out[row] = fmaxf(s + b2[0], 0.f);
}

// ---------------- launch ----------------
extern "C" void kernel_launch(void* const* d_in, const int* in_sizes, int n_in,
                              void* d_out, int out_size)
{
  const float* x       = (const float*)d_in[0];
  const int*   esrc    = (const int*)  d_in[1];
  const int*   edst    = (const int*)  d_in[2];
  const float* W_embed = (const float*)d_in[3];
  const float* W_gat   = (const float*)d_in[4];  // [4,64,64]
  const float* a_l     = (const float*)d_in[5];  // [4,1,64]
  const float* a_r     = (const float*)d_in[6];
  const float* W0      = (const float*)d_in[7];  // [256,64]
  const float* b0      = (const float*)d_in[8];
  const float* W1      = (const float*)d_in[9];
  const float* b1      = (const float*)d_in[10];
  const float* W2      = (const float*)d_in[11]; // [64,1]
  const float* b2      = (const float*)d_in[12];
  float* out = (float*)d_out;

  int n = in_sizes[0] / 128;   // N nodes (x is [N,128])
  int e = in_sizes[1];         // E edges

  float *h_ptr, *feat_ptr, *el_ptr, *er_ptr;
  cudaGetSymbolAddress((void**)&h_ptr,    g_h);
  cudaGetSymbolAddress((void**)&feat_ptr, g_feat);
  cudaGetSymbolAddress((void**)&el_ptr,   g_el);
  cudaGetSymbolAddress((void**)&er_ptr,   g_er);

  int gB = (n + 7) / 8;

  // embed: h = tanh(x @ W_embed)
  gemm_k<128, true, false><<<gB, 256>>>(x, W_embed, nullptr, nullptr,
                                        h_ptr, nullptr, nullptr, n);

  for (int l = 0; l < 4; ++l) {
    gemm_k<64, false, true><<<gB, 256>>>(h_ptr, W_gat + l*64*64,
                                         a_l + l*64, a_r + l*64,
                                         feat_ptr, el_ptr, er_ptr, n);
    init_k<<<(n*HID + 255)/256, 256>>>(n);
    edge_max_k<<<(e + 255)/256, 256>>>(esrc, edst, e, (l > 0) ? 1 : 0);
    edge_exp_k<<<(e + 255)/256, 256>>>(edst, e);
    edge_agg_k<<<((long long)e*16 + 255)/256, 256>>>(esrc, edst, e, (l == 0) ? 1 : 0);
    elu_k<<<(n*HID + 255)/256, 256>>>(n, l);
  }

  mlp_k<<<gB, 256>>>(W0, b0, W1, b1, W2, b2, out, n);
}

// round 2
// speedup vs baseline: 1.2116x; 1.2116x over previous
#include <cuda_runtime.h>
#include <math.h>

#define N_NODES 50000
#define N_EDGES 800000
#define HID 64

// ---------------- scratch (device globals) ----------------
__device__ float g_h[N_NODES*HID];        // current layer input
__device__ float g_feat[N_NODES*HID];     // h @ W_gat[l]
__device__ float g_fcat[N_NODES*4*HID];   // concat buffer [N,256]
__device__ float g_el[N_NODES];
__device__ float g_er[N_NODES];
__device__ float g_aexp[N_EDGES];         // per-CSR-slot scratch (scores -> exp)
__device__ unsigned char g_mask[N_EDGES]; // kept-edge mask, CSR order
__device__ int g_deg[N_NODES];
__device__ int g_off[N_NODES+1];
__device__ int g_pos[N_NODES];
__device__ int g_csr_src[N_EDGES];

// ---------------- GEMM: out[row,0:64] = act(A[row,:K] @ W[K,64]) ----------------
template<int K, bool TANH, bool ELER>
__global__ void gemm_k(const float* __restrict__ A, const float* __restrict__ W,
                       const float* __restrict__ al, const float* __restrict__ ar,
                       float* __restrict__ out, float* __restrict__ el, float* __restrict__ er,
                       int n)
{
  __shared__ float Wsh[K*64];
  int tid = threadIdx.x;
  for (int i = tid; i < K*64; i += blockDim.x) Wsh[i] = W[i];
  __syncthreads();
  int warp = tid >> 5, lane = tid & 31;
  int row = blockIdx.x * 8 + warp;
  if (row >= n) return;
  float acc0 = 0.f, acc1 = 0.f;
  #pragma unroll
  for (int kc = 0; kc < K; kc += 64) {
    float2 hv = *(const float2*)(A + (size_t)row*K + kc + 2*lane);
    #pragma unroll
    for (int kk = 0; kk < 64; ++kk) {
      float hk = __shfl_sync(0xffffffffu, (kk & 1) ? hv.y : hv.x, kk >> 1);
      acc0 = fmaf(hk, Wsh[(kc+kk)*64 + 2*lane],     acc0);
      acc1 = fmaf(hk, Wsh[(kc+kk)*64 + 2*lane + 1], acc1);
    }
  }
  if (TANH) { acc0 = tanhf(acc0); acc1 = tanhf(acc1); }
  out[(size_t)row*64 + 2*lane]     = acc0;
  out[(size_t)row*64 + 2*lane + 1] = acc1;
  if (ELER) {
    float pl = acc0*al[2*lane] + acc1*al[2*lane+1];
    float pr = acc0*ar[2*lane] + acc1*ar[2*lane+1];
    #pragma unroll
    for (int o = 16; o; o >>= 1) {
      pl += __shfl_xor_sync(0xffffffffu, pl, o);
      pr += __shfl_xor_sync(0xffffffffu, pr, o);
    }
    if (lane == 0) { el[row] = pl; er[row] = pr; }
  }
}

// ---------------- CSR build ----------------
__global__ void zero_deg_k(int n){
  int i = blockIdx.x*blockDim.x + threadIdx.x;
  if (i < n) g_deg[i] = 0;
}
__global__ void hist_k(const int* __restrict__ dst, int e){
  int i = blockIdx.x*blockDim.x + threadIdx.x;
  if (i < e) atomicAdd(&g_deg[dst[i]], 1);
}
// single-block scan over n degrees (n <= 50176 with 1024 threads x chunk 49)
__global__ void scan_k(int n, int e){
  __shared__ int ssum[1024];
  int tid = threadIdx.x;
  int chunk = (n + 1023) / 1024;
  int b = tid * chunk;
  int bend = min(b + chunk, n);
  int s = 0;
  for (int i = b; i < bend; ++i) s += g_deg[i];
  ssum[tid] = s;
  __syncthreads();
  // Hillis-Steele inclusive scan
  for (int d = 1; d < 1024; d <<= 1) {
    int t = (tid >= d) ? ssum[tid - d] : 0;
    __syncthreads();
    ssum[tid] += t;
    __syncthreads();
  }
  int off = ssum[tid] - s;  // exclusive
  for (int i = b; i < bend; ++i) {
    g_off[i] = off;
    g_pos[i] = off;
    off += g_deg[i];
  }
  if (tid == 0) g_off[n] = e;
}
__global__ void scatter_k(const int* __restrict__ src, const int* __restrict__ dst, int e){
  int i = blockIdx.x*blockDim.x + threadIdx.x;
  if (i >= e) return;
  int p = atomicAdd(&g_pos[dst[i]], 1);
  g_csr_src[p] = src[i];
}

// ---------------- fused per-layer edge kernel: one warp per dst node ----------------
// score + leaky_relu + mask + softmax (with max subtraction) + weighted aggregate
// + ELU + write h/fcat. No atomics.
__global__ void agg_k(int n, int layer){
  int tid = threadIdx.x, lane = tid & 31, warp = tid >> 5;
  int node = blockIdx.x * 8 + warp;
  if (node >= n) return;
  int beg = g_off[node], end = g_off[node+1];
  float erd = g_er[node];

  // pass 1: raw scores + segment max (lane-strided)
  float m = -1e30f;
  for (int j = beg + lane; j < end; j += 32) {
    int s = g_csr_src[j];
    float v = g_el[s] + erd;
    v = (v >= 0.f) ? v : 0.2f*v;
    if (layer > 0 && !g_mask[j]) v = -1e9f;
    g_aexp[j] = v;
    m = fmaxf(m, v);
  }
  #pragma unroll
  for (int o = 16; o; o >>= 1) m = fmaxf(m, __shfl_xor_sync(0xffffffffu, m, o));

  // pass 2: exp + segment sum
  float se = 0.f;
  for (int j = beg + lane; j < end; j += 32) {
    float a = expf(g_aexp[j] - m);
    g_aexp[j] = a;
    se += a;
  }
  #pragma unroll
  for (int o = 16; o; o >>= 1) se += __shfl_xor_sync(0xffffffffu, se, o);
  float inv = 1.f / fmaxf(se, 1e-9f);
  __syncwarp();   // make cross-lane g_aexp writes visible

  // pass 3: serial over edges, whole warp gathers feat[src] (256B coalesced)
  float acc0 = 0.f, acc1 = 0.f;
  for (int j = beg; j < end; ++j) {
    int s = g_csr_src[j];
    float a = g_aexp[j] * inv;
    if (layer == 0 && lane == 0) g_mask[j] = (a >= 0.01f) ? 1 : 0;
    float2 f = *(const float2*)(g_feat + (size_t)s*64 + 2*lane);
    acc0 = fmaf(a, f.x, acc0);
    acc1 = fmaf(a, f.y, acc1);
  }

  float o0 = (acc0 > 0.f) ? acc0 : expm1f(acc0);
  float o1 = (acc1 > 0.f) ? acc1 : expm1f(acc1);
  g_h[(size_t)node*64 + 2*lane]     = o0;
  g_h[(size_t)node*64 + 2*lane + 1] = o1;
  g_fcat[(size_t)node*256 + layer*64 + 2*lane]     = o0;
  g_fcat[(size_t)node*256 + layer*64 + 2*lane + 1] = o1;
}

// ---------------- fused MLP head: fcat[N,256] -> 64 -> 64 -> 1 ----------------
__global__ void mlp_k(const float* __restrict__ W0, const float* __restrict__ b0,
                      const float* __restrict__ W1, const float* __restrict__ b1,
                      const float* __restrict__ W2, const float* __restrict__ b2,
                      float* __restrict__ out, int n)
{
  __shared__ float Wsh[64*64];
  int tid = threadIdx.x, warp = tid >> 5, lane = tid & 31;
  int row = blockIdx.x * 8 + warp;
  int r = row < n ? row : (n - 1);
  float t0a = 0.f, t0b = 0.f;
  for (int kc = 0; kc < 256; kc += 64) {
    __syncthreads();
    for (int i = tid; i < 64*64; i += blockDim.x) Wsh[i] = W0[kc*64 + i];
    __syncthreads();
    float2 fv = *(const float2*)(g_fcat + (size_t)r*256 + kc + 2*lane);
    #pragma unroll
    for (int kk = 0; kk < 64; ++kk) {
      float fk = __shfl_sync(0xffffffffu, (kk & 1) ? fv.y : fv.x, kk >> 1);
      t0a = fmaf(fk, Wsh[kk*64 + 2*lane],     t0a);
      t0b = fmaf(fk, Wsh[kk*64 + 2*lane + 1], t0b);
    }
  }
  t0a = fmaxf(t0a + b0[2*lane],     0.f);
  t0b = fmaxf(t0b + b0[2*lane + 1], 0.f);
  __syncthreads();
  for (int i = tid; i < 64*64; i += blockDim.x) Wsh[i] = W1[i];
  __syncthreads();
  float t1a = 0.f, t1b = 0.f;
  #pragma unroll
  for (int kk = 0; kk < 64; ++kk) {
    float fk = __shfl_sync(0xffffffffu, (kk & 1) ? t0b : t0a, kk >> 1);
    t1a = fmaf(fk, Wsh[kk*64 + 2*lane],     t1a);
    t1b = fmaf(fk, Wsh[kk*64 + 2*lane + 1], t1b);
  }
  t1a = fmaxf(t1a + b1[2*lane],     0.f);
  t1b = fmaxf(t1b + b1[2*lane + 1], 0.f);
  float s = t1a*W2[2*lane] + t1b*W2[2*lane + 1];
  #pragma unroll
  for (int o = 16; o; o >>= 1) s += __shfl_xor_sync(0xffffffffu, s, o);
  if (lane == 0 && row < n) out[row] = fmaxf(s + b2[0], 0.f);
}

// ---------------- launch ----------------
extern "C" void kernel_launch(void* const* d_in, const int* in_sizes, int n_in,
                              void* d_out, int out_size)
{
  const float* x       = (const float*)d_in[0];
  const int*   esrc    = (const int*)  d_in[1];
  const int*   edst    = (const int*)  d_in[2];
  const float* W_embed = (const float*)d_in[3];
  const float* W_gat   = (const float*)d_in[4];  // [4,64,64]
  const float* a_l     = (const float*)d_in[5];  // [4,1,64]
  const float* a_r     = (const float*)d_in[6];
  const float* W0      = (const float*)d_in[7];  // [256,64]
  const float* b0      = (const float*)d_in[8];
  const float* W1      = (const float*)d_in[9];
  const float* b1      = (const float*)d_in[10];
  const float* W2      = (const float*)d_in[11]; // [64,1]
  const float* b2      = (const float*)d_in[12];
  float* out = (float*)d_out;

  int n = in_sizes[0] / 128;   // N nodes
  int e = in_sizes[1];         // E edges

  float *h_ptr, *feat_ptr, *el_ptr, *er_ptr;
  cudaGetSymbolAddress((void**)&h_ptr,    g_h);
  cudaGetSymbolAddress((void**)&feat_ptr, g_feat);
  cudaGetSymbolAddress((void**)&el_ptr,   g_el);
  cudaGetSymbolAddress((void**)&er_ptr,   g_er);

  int gB = (n + 7) / 8;

  // CSR build (overlaps nothing, but embed GEMM below is independent stream-ordered work)
  zero_deg_k<<<(n + 255)/256, 256>>>(n);
  hist_k<<<(e + 255)/256, 256>>>(edst, e);
  scan_k<<<1, 1024>>>(n, e);
  scatter_k<<<(e + 255)/256, 256>>>(esrc, edst, e);

  // embed: h = tanh(x @ W_embed)
  gemm_k<128, true, false><<<gB, 256>>>(x, W_embed, nullptr, nullptr,
                                        h_ptr, nullptr, nullptr, n);

  for (int l = 0; l < 4; ++l) {
    gemm_k<64, false, true><<<gB, 256>>>(h_ptr, W_gat + l*64*64,
                                         a_l + l*64, a_r + l*64,
                                         feat_ptr, el_ptr, er_ptr, n);
    agg_k<<<gB, 256>>>(n, l);
  }

  mlp_k<<<gB, 256>>>(W0, b0, W1, b1, W2, b2, out, n);
}

// round 3
// speedup vs baseline: 2.0073x; 1.6568x over previous
#include <cuda_runtime.h>
#include <math.h>

#define N_NODES 50000
#define N_EDGES 800000
#define HID 64

// ---------------- scratch (device globals) ----------------
__device__ float g_h[N_NODES*HID];        // current layer input / MLP tmp1
__device__ float g_feat[N_NODES*HID];     // h @ W_gat[l] / MLP tmp0
__device__ float g_fcat[N_NODES*4*HID];   // concat buffer [N,256]
__device__ float g_el[N_NODES];
__device__ float g_er[N_NODES];
__device__ float g_aexp[N_EDGES];
__device__ unsigned char g_mask[N_EDGES];
__device__ int g_deg[N_NODES];
__device__ int g_off[N_NODES+1];
__device__ int g_pos[N_NODES];
__device__ int g_csr_src[N_EDGES];

// ---------------- packed f32x2 helpers (sm_103a FFMA2) ----------------
__device__ __forceinline__ unsigned long long ffma2(unsigned long long a,
                                                    unsigned long long b,
                                                    unsigned long long c){
  unsigned long long d;
  asm("fma.rn.f32x2 %0, %1, %2, %3;" : "=l"(d) : "l"(a), "l"(b), "l"(c));
  return d;
}
__device__ __forceinline__ unsigned long long packff(float x){
  unsigned long long u;
  asm("mov.b64 %0, {%1, %1};" : "=l"(u) : "f"(x));
  return u;
}
__device__ __forceinline__ float2 unpackff(unsigned long long u){
  float2 f;
  asm("mov.b64 {%0, %1}, %2;" : "=f"(f.x), "=f"(f.y) : "l"(u));
  return f;
}

// ---------------- register-tiled GEMM with f32x2 FMA ----------------
// C[n,64] = act(A[n,K] @ W[K,64] (+bias))
// tile: 128 rows x 64 cols per block (256 threads).
// thread: c0 = tid&31 (cols c0, c0+32), rb = tid>>5 (rows rb*16 .. rb*16+15)
// A chunk stored TRANSPOSED in smem (As[k][r], 2-way swizzle) so one broadcast
// LDS.128 yields two pre-packed f32x2 row-pairs. ACT: 0=none, 1=tanh, 2=bias+relu
template<int K, int ACT>
__global__ void gemm2_k(const float* __restrict__ A, const float* __restrict__ W,
                        const float* __restrict__ bias, float* __restrict__ out, int n)
{
  __shared__ float As[64][128];
  __shared__ float Ws[64][64];
  int tid = threadIdx.x;
  int c0 = tid & 31, rb = tid >> 5;
  int row0 = blockIdx.x * 128;

  unsigned long long acc[8][2];
  #pragma unroll
  for (int p = 0; p < 8; ++p) { acc[p][0] = 0ull; acc[p][1] = 0ull; }

  for (int kc = 0; kc < K; kc += 64) {
    __syncthreads();
    // load A chunk (coalesced) -> transposed smem with swizzle
    #pragma unroll
    for (int j = 0; j < 8; ++j) {
      int idx = tid + 256*j;            // 2048 float4 slots
      int r  = idx >> 4;                // 0..127
      int k0 = (idx & 15) * 4;          // 0..60
      float4 v = make_float4(0.f,0.f,0.f,0.f);
      int grow = row0 + r;
      if (grow < n) v = *(const float4*)(A + (size_t)grow*K + kc + k0);
      int rs = r ^ (4*((k0 >> 2) & 7));
      As[k0+0][rs] = v.x; As[k0+1][rs] = v.y;
      As[k0+2][rs] = v.z; As[k0+3][rs] = v.w;
    }
    // load W chunk (straight copy)
    #pragma unroll
    for (int j = 0; j < 4; ++j) {
      int idx = tid + 256*j;            // 1024 float4 slots
      int kr = idx >> 4, cq = (idx & 15) * 4;
      *(float4*)&Ws[kr][cq] = *(const float4*)(W + (size_t)(kc+kr)*64 + cq);
    }
    __syncthreads();

    #pragma unroll 4
    for (int k = 0; k < 64; ++k) {
      unsigned long long w0 = packff(Ws[k][c0]);
      unsigned long long w1 = packff(Ws[k][c0+32]);
      int v = 4*((k >> 2) & 7);
      #pragma unroll
      for (int u = 0; u < 4; ++u) {
        int rr = (rb*16 + 4*u) ^ v;
        ulonglong2 av = *(const ulonglong2*)&As[k][rr];
        acc[2*u  ][0] = ffma2(av.x, w0, acc[2*u  ][0]);
        acc[2*u  ][1] = ffma2(av.x, w1, acc[2*u  ][1]);
        acc[2*u+1][0] = ffma2(av.y, w0, acc[2*u+1][0]);
        acc[2*u+1][1] = ffma2(av.y, w1, acc[2*u+1][1]);
      }
    }
  }

  float b0v = 0.f, b1v = 0.f;
  if (ACT == 2) { b0v = bias[c0]; b1v = bias[c0+32]; }
  #pragma unroll
  for (int p = 0; p < 8; ++p) {
    int r = row0 + rb*16 + 2*p;
    float2 va = unpackff(acc[p][0]);   // rows (r, r+1) @ col c0
    float2 vb = unpackff(acc[p][1]);   // rows (r, r+1) @ col c0+32
    float o00 = va.x, o01 = vb.x, o10 = va.y, o11 = vb.y;
    if (ACT == 1) { o00 = tanhf(o00); o01 = tanhf(o01); o10 = tanhf(o10); o11 = tanhf(o11); }
    if (ACT == 2) {
      o00 = fmaxf(o00 + b0v, 0.f); o01 = fmaxf(o01 + b1v, 0.f);
      o10 = fmaxf(o10 + b0v, 0.f); o11 = fmaxf(o11 + b1v, 0.f);
    }
    if (r < n)     { out[(size_t)r*64 + c0] = o00;     out[(size_t)r*64 + c0 + 32] = o01; }
    if (r + 1 < n) { out[(size_t)(r+1)*64 + c0] = o10; out[(size_t)(r+1)*64 + c0 + 32] = o11; }
  }
}

// ---------------- el/er: per-row dot with attention vectors ----------------
__global__ void eler_k(const float* __restrict__ al, const float* __restrict__ ar, int n){
  int tid = threadIdx.x, lane = tid & 31, warp = tid >> 5;
  int row = blockIdx.x * 8 + warp;
  if (row >= n) return;
  float f0 = g_feat[(size_t)row*64 + lane];
  float f1 = g_feat[(size_t)row*64 + 32 + lane];
  float pl = f0*al[lane] + f1*al[lane+32];
  float pr = f0*ar[lane] + f1*ar[lane+32];
  #pragma unroll
  for (int o = 16; o; o >>= 1) {
    pl += __shfl_xor_sync(0xffffffffu, pl, o);
    pr += __shfl_xor_sync(0xffffffffu, pr, o);
  }
  if (lane == 0) { g_el[row] = pl; g_er[row] = pr; }
}

// ---------------- CSR build ----------------
__global__ void zero_deg_k(int n){
  int i = blockIdx.x*blockDim.x + threadIdx.x;
  if (i < n) g_deg[i] = 0;
}
__global__ void hist_k(const int* __restrict__ dst, int e){
  int i = blockIdx.x*blockDim.x + threadIdx.x;
  if (i < e) atomicAdd(&g_deg[dst[i]], 1);
}
__global__ void scan_k(int n, int e){
  __shared__ int ssum[1024];
  int tid = threadIdx.x;
  int chunk = (n + 1023) / 1024;
  int b = tid * chunk;
  int bend = min(b + chunk, n);
  int s = 0;
  for (int i = b; i < bend; ++i) s += g_deg[i];
  ssum[tid] = s;
  __syncthreads();
  for (int d = 1; d < 1024; d <<= 1) {
    int t = (tid >= d) ? ssum[tid - d] : 0;
    __syncthreads();
    ssum[tid] += t;
    __syncthreads();
  }
  int off = ssum[tid] - s;
  for (int i = b; i < bend; ++i) {
    g_off[i] = off;
    g_pos[i] = off;
    off += g_deg[i];
  }
  if (tid == 0) g_off[n] = e;
}
__global__ void scatter_k(const int* __restrict__ src, const int* __restrict__ dst, int e){
  int i = blockIdx.x*blockDim.x + threadIdx.x;
  if (i >= e) return;
  int p = atomicAdd(&g_pos[dst[i]], 1);
  g_csr_src[p] = src[i];
}

// ---------------- fused per-layer edge kernel: one warp per dst node ----------------
__global__ void agg_k(int n, int layer){
  int tid = threadIdx.x, lane = tid & 31, warp = tid >> 5;
  int node = blockIdx.x * 8 + warp;
  if (node >= n) return;
  int beg = g_off[node], end = g_off[node+1];
  float erd = g_er[node];

  // pass 1: raw scores + segment max
  float m = -1e30f;
  for (int j = beg + lane; j < end; j += 32) {
    int s = g_csr_src[j];
    float v = g_el[s] + erd;
    v = (v >= 0.f) ? v : 0.2f*v;
    if (layer > 0 && !g_mask[j]) v = -1e9f;
    g_aexp[j] = v;
    m = fmaxf(m, v);
  }
  #pragma unroll
  for (int o = 16; o; o >>= 1) m = fmaxf(m, __shfl_xor_sync(0xffffffffu, m, o));

  // pass 2: exp + segment sum
  float se = 0.f;
  for (int j = beg + lane; j < end; j += 32) {
    float a = expf(g_aexp[j] - m);
    g_aexp[j] = a;
    se += a;
  }
  #pragma unroll
  for (int o = 16; o; o >>= 1) se += __shfl_xor_sync(0xffffffffu, se, o);
  float inv = 1.f / fmaxf(se, 1e-9f);
  __syncwarp();

  // layer-0 mask write (lane-parallel)
  if (layer == 0) {
    for (int j = beg + lane; j < end; j += 32)
      g_mask[j] = (g_aexp[j]*inv >= 0.01f) ? 1 : 0;
  }

  // pass 3: 4-way unrolled weighted gather (MLP=4 on dependent ld chains)
  float acc0 = 0.f, acc1 = 0.f;
  int j = beg;
  for (; j + 4 <= end; j += 4) {
    int s0 = g_csr_src[j], s1 = g_csr_src[j+1], s2 = g_csr_src[j+2], s3 = g_csr_src[j+3];
    float a0 = g_aexp[j]*inv,   a1 = g_aexp[j+1]*inv;
    float a2 = g_aexp[j+2]*inv, a3 = g_aexp[j+3]*inv;
    float2 f0 = *(const float2*)(g_feat + (size_t)s0*64 + 2*lane);
    float2 f1 = *(const float2*)(g_feat + (size_t)s1*64 + 2*lane);
    float2 f2 = *(const float2*)(g_feat + (size_t)s2*64 + 2*lane);
    float2 f3 = *(const float2*)(g_feat + (size_t)s3*64 + 2*lane);
    acc0 = fmaf(a0, f0.x, acc0); acc1 = fmaf(a0, f0.y, acc1);
    acc0 = fmaf(a1, f1.x, acc0); acc1 = fmaf(a1, f1.y, acc1);
    acc0 = fmaf(a2, f2.x, acc0); acc1 = fmaf(a2, f2.y, acc1);
    acc0 = fmaf(a3, f3.x, acc0); acc1 = fmaf(a3, f3.y, acc1);
  }
  for (; j < end; ++j) {
    int s = g_csr_src[j];
    float a = g_aexp[j]*inv;
    float2 f = *(const float2*)(g_feat + (size_t)s*64 + 2*lane);
    acc0 = fmaf(a, f.x, acc0); acc1 = fmaf(a, f.y, acc1);
  }

  float o0 = (acc0 > 0.f) ? acc0 : expm1f(acc0);
  float o1 = (acc1 > 0.f) ? acc1 : expm1f(acc1);
  g_h[(size_t)node*64 + 2*lane]     = o0;
  g_h[(size_t)node*64 + 2*lane + 1] = o1;
  g_fcat[(size_t)node*256 + layer*64 + 2*lane]     = o0;
  g_fcat[(size_t)node*256 + layer*64 + 2*lane + 1] = o1;
}

// ---------------- final 64 -> 1 layer ----------------
__global__ void mlp2_k(const float* __restrict__ T, const float* __restrict__ W2,
                       const float* __restrict__ b2, float* __restrict__ out, int n){
  int tid = threadIdx.x, lane = tid & 31, warp = tid >> 5;
  int row = blockIdx.x * 8 + warp;
  if (row >= n) return;
  float s = T[(size_t)row*64 + lane]*W2[lane] + T[(size_t)row*64 + 32 + lane]*W2[lane+32];
  #pragma unroll
  for (int o = 16; o; o >>= 1) s += __shfl_xor_sync(0xffffffffu, s, o);
  if (lane == 0) out[row] = fmaxf(s + b2[0], 0.f);
}

// ---------------- launch ----------------
extern "C" void kernel_launch(void* const* d_in, const int* in_sizes, int n_in,
                              void* d_out, int out_size)
{
  const float* x       = (const float*)d_in[0];
  const int*   esrc    = (const int*)  d_in[1];
  const int*   edst    = (const int*)  d_in[2];
  const float* W_embed = (const float*)d_in[3];
  const float* W_gat   = (const float*)d_in[4];  // [4,64,64]
  const float* a_l     = (const float*)d_in[5];  // [4,1,64]
  const float* a_r     = (const float*)d_in[6];
  const float* W0      = (const float*)d_in[7];  // [256,64]
  const float* b0      = (const float*)d_in[8];
  const float* W1      = (const float*)d_in[9];
  const float* b1      = (const float*)d_in[10];
  const float* W2      = (const float*)d_in[11]; // [64,1]
  const float* b2      = (const float*)d_in[12];
  float* out = (float*)d_out;

  int n = in_sizes[0] / 128;   // N nodes
  int e = in_sizes[1];         // E edges

  float *h_ptr, *feat_ptr, *fcat_ptr;
  cudaGetSymbolAddress((void**)&h_ptr,    g_h);
  cudaGetSymbolAddress((void**)&feat_ptr, g_feat);
  cudaGetSymbolAddress((void**)&fcat_ptr, g_fcat);

  int tiles = (n + 127) / 128;
  int gW = (n + 7) / 8;

  // CSR build
  zero_deg_k<<<(n + 255)/256, 256>>>(n);
  hist_k<<<(e + 255)/256, 256>>>(edst, e);
  scan_k<<<1, 1024>>>(n, e);
  scatter_k<<<(e + 255)/256, 256>>>(esrc, edst, e);

  // embed: h = tanh(x @ W_embed)
  gemm2_k<128, 1><<<tiles, 256>>>(x, W_embed, nullptr, h_ptr, n);

  for (int l = 0; l < 4; ++l) {
    gemm2_k<64, 0><<<tiles, 256>>>(h_ptr, W_gat + l*64*64, nullptr, feat_ptr, n);
    eler_k<<<gW, 256>>>(a_l + l*64, a_r + l*64, n);
    agg_k<<<gW, 256>>>(n, l);
  }

  // MLP head: fcat -> 64 (relu) -> 64 (relu) -> 1 (relu)
  gemm2_k<256, 2><<<tiles, 256>>>(fcat_ptr, W0, b0, feat_ptr, n);
  gemm2_k<64,  2><<<tiles, 256>>>(feat_ptr, W1, b1, h_ptr, n);
  mlp2_k<<<gW, 256>>>(h_ptr, W2, b2, out, n);
}

// round 4
// speedup vs baseline: 2.3783x; 1.1848x over previous
#include <cuda_runtime.h>
#include <math.h>

#define N_NODES 50000
#define N_EDGES 800000
#define HID 64
#define SCAN_BLOCKS 128

// ---------------- scratch (device globals) ----------------
__device__ float g_h[N_NODES*HID];
__device__ float g_feat[N_NODES*HID];
__device__ float g_fcat[N_NODES*4*HID];
__device__ float g_el[N_NODES];
__device__ float g_er[N_NODES];
__device__ float g_aexp[N_EDGES];         // only used by the rare deg>32 path
__device__ unsigned char g_mask[N_EDGES];
__device__ int g_deg[N_NODES];
__device__ int g_off[N_NODES+1];
__device__ int g_pos[N_NODES];
__device__ int g_csr_src[N_EDGES];
__device__ int g_bsum[SCAN_BLOCKS];

// ---------------- packed f32x2 helpers ----------------
__device__ __forceinline__ unsigned long long ffma2(unsigned long long a,
                                                    unsigned long long b,
                                                    unsigned long long c){
  unsigned long long d;
  asm("fma.rn.f32x2 %0, %1, %2, %3;" : "=l"(d) : "l"(a), "l"(b), "l"(c));
  return d;
}
__device__ __forceinline__ unsigned long long packff(float x){
  unsigned long long u;
  asm("mov.b64 %0, {%1, %1};" : "=l"(u) : "f"(x));
  return u;
}
__device__ __forceinline__ float2 unpackff(unsigned long long u){
  float2 f;
  asm("mov.b64 {%0, %1}, %2;" : "=f"(f.x), "=f"(f.y) : "l"(u));
  return f;
}

// ---------------- register-tiled GEMM with f32x2 FMA ----------------
template<int K, int ACT>
__global__ void gemm2_k(const float* __restrict__ A, const float* __restrict__ W,
                        const float* __restrict__ bias, float* __restrict__ out, int n)
{
  __shared__ float As[64][128];
  __shared__ float Ws[64][64];
  int tid = threadIdx.x;
  int c0 = tid & 31, rb = tid >> 5;
  int row0 = blockIdx.x * 128;

  unsigned long long acc[8][2];
  #pragma unroll
  for (int p = 0; p < 8; ++p) { acc[p][0] = 0ull; acc[p][1] = 0ull; }

  for (int kc = 0; kc < K; kc += 64) {
    __syncthreads();
    #pragma unroll
    for (int j = 0; j < 8; ++j) {
      int idx = tid + 256*j;
      int r  = idx >> 4;
      int k0 = (idx & 15) * 4;
      float4 v = make_float4(0.f,0.f,0.f,0.f);
      int grow = row0 + r;
      if (grow < n) v = *(const float4*)(A + (size_t)grow*K + kc + k0);
      int rs = r ^ (4*((k0 >> 2) & 7));
      As[k0+0][rs] = v.x; As[k0+1][rs] = v.y;
      As[k0+2][rs] = v.z; As[k0+3][rs] = v.w;
    }
    #pragma unroll
    for (int j = 0; j < 4; ++j) {
      int idx = tid + 256*j;
      int kr = idx >> 4, cq = (idx & 15) * 4;
      *(float4*)&Ws[kr][cq] = *(const float4*)(W + (size_t)(kc+kr)*64 + cq);
    }
    __syncthreads();

    #pragma unroll 4
    for (int k = 0; k < 64; ++k) {
      unsigned long long w0 = packff(Ws[k][c0]);
      unsigned long long w1 = packff(Ws[k][c0+32]);
      int v = 4*((k >> 2) & 7);
      #pragma unroll
      for (int u = 0; u < 4; ++u) {
        int rr = (rb*16 + 4*u) ^ v;
        ulonglong2 av = *(const ulonglong2*)&As[k][rr];
        acc[2*u  ][0] = ffma2(av.x, w0, acc[2*u  ][0]);
        acc[2*u  ][1] = ffma2(av.x, w1, acc[2*u  ][1]);
        acc[2*u+1][0] = ffma2(av.y, w0, acc[2*u+1][0]);
        acc[2*u+1][1] = ffma2(av.y, w1, acc[2*u+1][1]);
      }
    }
  }

  float b0v = 0.f, b1v = 0.f;
  if (ACT == 2) { b0v = bias[c0]; b1v = bias[c0+32]; }
  #pragma unroll
  for (int p = 0; p < 8; ++p) {
    int r = row0 + rb*16 + 2*p;
    float2 va = unpackff(acc[p][0]);
    float2 vb = unpackff(acc[p][1]);
    float o00 = va.x, o01 = vb.x, o10 = va.y, o11 = vb.y;
    if (ACT == 1) { o00 = tanhf(o00); o01 = tanhf(o01); o10 = tanhf(o10); o11 = tanhf(o11); }
    if (ACT == 2) {
      o00 = fmaxf(o00 + b0v, 0.f); o01 = fmaxf(o01 + b1v, 0.f);
      o10 = fmaxf(o10 + b0v, 0.f); o11 = fmaxf(o11 + b1v, 0.f);
    }
    if (r < n)     { out[(size_t)r*64 + c0] = o00;     out[(size_t)r*64 + c0 + 32] = o01; }
    if (r + 1 < n) { out[(size_t)(r+1)*64 + c0] = o10; out[(size_t)(r+1)*64 + c0 + 32] = o11; }
  }
}

// ---------------- el/er ----------------
__global__ void eler_k(const float* __restrict__ al, const float* __restrict__ ar, int n){
  int tid = threadIdx.x, lane = tid & 31, warp = tid >> 5;
  int row = blockIdx.x * 8 + warp;
  if (row >= n) return;
  float f0 = g_feat[(size_t)row*64 + lane];
  float f1 = g_feat[(size_t)row*64 + 32 + lane];
  float pl = f0*al[lane] + f1*al[lane+32];
  float pr = f0*ar[lane] + f1*ar[lane+32];
  #pragma unroll
  for (int o = 16; o; o >>= 1) {
    pl += __shfl_xor_sync(0xffffffffu, pl, o);
    pr += __shfl_xor_sync(0xffffffffu, pr, o);
  }
  if (lane == 0) { g_el[row] = pl; g_er[row] = pr; }
}

// ---------------- CSR build ----------------
__global__ void zero_deg_k(int n){
  int i = blockIdx.x*blockDim.x + threadIdx.x;
  if (i < n) g_deg[i] = 0;
}
__global__ void hist_k(const int* __restrict__ dst, int e){
  int i = 4*(blockIdx.x*blockDim.x + threadIdx.x);
  if (i + 4 <= e) {
    int4 d = *(const int4*)(dst + i);
    atomicAdd(&g_deg[d.x], 1); atomicAdd(&g_deg[d.y], 1);
    atomicAdd(&g_deg[d.z], 1); atomicAdd(&g_deg[d.w], 1);
  } else {
    for (int j = i; j < e; ++j) atomicAdd(&g_deg[dst[j]], 1);
  }
}
// 3-phase multi-block scan
__global__ void scan1_k(int n){
  __shared__ int ss[256];
  int per = (n + SCAN_BLOCKS - 1) / SCAN_BLOCKS;
  int b0 = blockIdx.x*per, b1 = min(b0+per, n);
  int s = 0;
  for (int i = b0 + threadIdx.x; i < b1; i += 256) s += g_deg[i];
  ss[threadIdx.x] = s;
  __syncthreads();
  for (int o = 128; o; o >>= 1) {
    if (threadIdx.x < o) ss[threadIdx.x] += ss[threadIdx.x + o];
    __syncthreads();
  }
  if (threadIdx.x == 0) g_bsum[blockIdx.x] = ss[0];
}
__global__ void scan2_k(){
  __shared__ int sh[SCAN_BLOCKS];
  int tid = threadIdx.x;
  int v = g_bsum[tid];
  sh[tid] = v;
  __syncthreads();
  for (int d = 1; d < SCAN_BLOCKS; d <<= 1) {
    int t = (tid >= d) ? sh[tid-d] : 0;
    __syncthreads();
    sh[tid] += t;
    __syncthreads();
  }
  g_bsum[tid] = sh[tid] - v;   // exclusive
}
__global__ void scan3_k(int n, int e){
  __shared__ int ss[256];
  int per = (n + SCAN_BLOCKS - 1) / SCAN_BLOCKS;
  int b0 = blockIdx.x*per, b1 = min(b0+per, n);
  int len = b1 - b0;
  int chunk = (len + 255) / 256;
  int t0 = b0 + threadIdx.x*chunk, t1 = min(t0 + chunk, b1);
  int s = 0;
  for (int i = t0; i < t1; ++i) s += g_deg[i];
  ss[threadIdx.x] = s;
  __syncthreads();
  for (int d = 1; d < 256; d <<= 1) {
    int t = (threadIdx.x >= d) ? ss[threadIdx.x-d] : 0;
    __syncthreads();
    ss[threadIdx.x] += t;
    __syncthreads();
  }
  int off = g_bsum[blockIdx.x] + ss[threadIdx.x] - s;
  for (int i = t0; i < t1; ++i) {
    g_off[i] = off; g_pos[i] = off; off += g_deg[i];
  }
  if (blockIdx.x == 0 && threadIdx.x == 0) g_off[n] = e;
}
__global__ void scatter_k(const int* __restrict__ src, const int* __restrict__ dst, int e){
  int i = 4*(blockIdx.x*blockDim.x + threadIdx.x);
  if (i + 4 <= e) {
    int4 d = *(const int4*)(dst + i);
    int4 s = *(const int4*)(src + i);
    int p0 = atomicAdd(&g_pos[d.x], 1);
    int p1 = atomicAdd(&g_pos[d.y], 1);
    int p2 = atomicAdd(&g_pos[d.z], 1);
    int p3 = atomicAdd(&g_pos[d.w], 1);
    g_csr_src[p0] = s.x; g_csr_src[p1] = s.y;
    g_csr_src[p2] = s.z; g_csr_src[p3] = s.w;
  } else {
    for (int j = i; j < e; ++j) {
      int p = atomicAdd(&g_pos[dst[j]], 1);
      g_csr_src[p] = src[j];
    }
  }
}

// ---------------- fused per-layer edge kernel ----------------
__global__ void agg_k(int n, int layer){
  int tid = threadIdx.x, lane = tid & 31, warp = tid >> 5;
  int node = blockIdx.x * 8 + warp;
  if (node >= n) return;
  int beg = g_off[node], end = g_off[node+1];
  int deg = end - beg;
  float erd = g_er[node];

  if (deg <= 32) {
    // ---- register-resident softmax: one edge per lane ----
    int s = 0; float v = -1e30f;
    if (lane < deg) {
      s = g_csr_src[beg + lane];
      v = g_el[s] + erd;
      v = (v >= 0.f) ? v : 0.2f*v;
      if (layer > 0 && !g_mask[beg + lane]) v = -1e9f;
    }
    float m = v;
    #pragma unroll
    for (int o = 16; o; o >>= 1) m = fmaxf(m, __shfl_xor_sync(0xffffffffu, m, o));
    float a = (lane < deg) ? expf(v - m) : 0.f;
    float se = a;
    #pragma unroll
    for (int o = 16; o; o >>= 1) se += __shfl_xor_sync(0xffffffffu, se, o);
    float alpha = a / fmaxf(se, 1e-9f);
    if (layer == 0 && lane < deg) g_mask[beg + lane] = (alpha >= 0.01f) ? 1 : 0;
    if (alpha == 0.f) s = 0;   // dead loads hit feat[0] (L1-hot)

    // ---- gather: 2 edges per warp iteration via LDG.128, 4-pair unroll ----
    int half = lane >> 4, q = lane & 15;
    const float* fb = g_feat + q*4;
    float4 acc = make_float4(0.f, 0.f, 0.f, 0.f);
    int npair = (deg + 1) >> 1;
    int p = 0;
    for (; p + 4 <= npair; p += 4) {
      int j0 = 2*p + half, j1 = j0 + 2, j2 = j0 + 4, j3 = j0 + 6;
      int s0 = __shfl_sync(0xffffffffu, s, j0);
      int s1 = __shfl_sync(0xffffffffu, s, j1);
      int s2 = __shfl_sync(0xffffffffu, s, j2);
      int s3 = __shfl_sync(0xffffffffu, s, j3);
      float a0 = __shfl_sync(0xffffffffu, alpha, j0);
      float a1 = __shfl_sync(0xffffffffu, alpha, j1);
      float a2 = __shfl_sync(0xffffffffu, alpha, j2);
      float a3 = __shfl_sync(0xffffffffu, alpha, j3);
      float4 f0 = *(const float4*)(fb + (size_t)s0*64);
      float4 f1 = *(const float4*)(fb + (size_t)s1*64);
      float4 f2 = *(const float4*)(fb + (size_t)s2*64);
      float4 f3 = *(const float4*)(fb + (size_t)s3*64);
      acc.x = fmaf(a0, f0.x, acc.x); acc.y = fmaf(a0, f0.y, acc.y);
      acc.z = fmaf(a0, f0.z, acc.z); acc.w = fmaf(a0, f0.w, acc.w);
      acc.x = fmaf(a1, f1.x, acc.x); acc.y = fmaf(a1, f1.y, acc.y);
      acc.z = fmaf(a1, f1.z, acc.z); acc.w = fmaf(a1, f1.w, acc.w);
      acc.x = fmaf(a2, f2.x, acc.x); acc.y = fmaf(a2, f2.y, acc.y);
      acc.z = fmaf(a2, f2.z, acc.z); acc.w = fmaf(a2, f2.w, acc.w);
      acc.x = fmaf(a3, f3.x, acc.x); acc.y = fmaf(a3, f3.y, acc.y);
      acc.z = fmaf(a3, f3.z, acc.z); acc.w = fmaf(a3, f3.w, acc.w);
    }
    for (; p < npair; ++p) {
      int j = 2*p + half;
      int sj = __shfl_sync(0xffffffffu, s, j);
      float aj = __shfl_sync(0xffffffffu, alpha, j);
      float4 f = *(const float4*)(fb + (size_t)sj*64);
      acc.x = fmaf(aj, f.x, acc.x); acc.y = fmaf(aj, f.y, acc.y);
      acc.z = fmaf(aj, f.z, acc.z); acc.w = fmaf(aj, f.w, acc.w);
    }
    // fold the two halves
    acc.x += __shfl_xor_sync(0xffffffffu, acc.x, 16);
    acc.y += __shfl_xor_sync(0xffffffffu, acc.y, 16);
    acc.z += __shfl_xor_sync(0xffffffffu, acc.z, 16);
    acc.w += __shfl_xor_sync(0xffffffffu, acc.w, 16);
    if (half == 0) {
      float4 o;
      o.x = (acc.x > 0.f) ? acc.x : expm1f(acc.x);
      o.y = (acc.y > 0.f) ? acc.y : expm1f(acc.y);
      o.z = (acc.z > 0.f) ? acc.z : expm1f(acc.z);
      o.w = (acc.w > 0.f) ? acc.w : expm1f(acc.w);
      *(float4*)(g_h    + (size_t)node*64  + q*4) = o;
      *(float4*)(g_fcat + (size_t)node*256 + layer*64 + q*4) = o;
    }
  } else {
    // ---- rare fallback: deg > 32, 3-pass with global scratch ----
    float m = -1e30f;
    for (int j = beg + lane; j < end; j += 32) {
      int s = g_csr_src[j];
      float v = g_el[s] + erd;
      v = (v >= 0.f) ? v : 0.2f*v;
      if (layer > 0 && !g_mask[j]) v = -1e9f;
      g_aexp[j] = v;
      m = fmaxf(m, v);
    }
    #pragma unroll
    for (int o = 16; o; o >>= 1) m = fmaxf(m, __shfl_xor_sync(0xffffffffu, m, o));
    float se = 0.f;
    for (int j = beg + lane; j < end; j += 32) {
      float a = expf(g_aexp[j] - m);
      g_aexp[j] = a;
      se += a;
    }
    #pragma unroll
    for (int o = 16; o; o >>= 1) se += __shfl_xor_sync(0xffffffffu, se, o);
    float inv = 1.f / fmaxf(se, 1e-9f);
    __syncwarp();
    if (layer == 0) {
      for (int j = beg + lane; j < end; j += 32)
        g_mask[j] = (g_aexp[j]*inv >= 0.01f) ? 1 : 0;
    }
    float acc0 = 0.f, acc1 = 0.f;
    int j = beg;
    for (; j + 4 <= end; j += 4) {
      int s0 = g_csr_src[j], s1 = g_csr_src[j+1], s2 = g_csr_src[j+2], s3 = g_csr_src[j+3];
      float a0 = g_aexp[j]*inv,   a1 = g_aexp[j+1]*inv;
      float a2 = g_aexp[j+2]*inv, a3 = g_aexp[j+3]*inv;
      float2 f0 = *(const float2*)(g_feat + (size_t)s0*64 + 2*lane);
      float2 f1 = *(const float2*)(g_feat + (size_t)s1*64 + 2*lane);
      float2 f2 = *(const float2*)(g_feat + (size_t)s2*64 + 2*lane);
      float2 f3 = *(const float2*)(g_feat + (size_t)s3*64 + 2*lane);
      acc0 = fmaf(a0, f0.x, acc0); acc1 = fmaf(a0, f0.y, acc1);
      acc0 = fmaf(a1, f1.x, acc0); acc1 = fmaf(a1, f1.y, acc1);
      acc0 = fmaf(a2, f2.x, acc0); acc1 = fmaf(a2, f2.y, acc1);
      acc0 = fmaf(a3, f3.x, acc0); acc1 = fmaf(a3, f3.y, acc1);
    }
    for (; j < end; ++j) {
      int s = g_csr_src[j];
      float a = g_aexp[j]*inv;
      float2 f = *(const float2*)(g_feat + (size_t)s*64 + 2*lane);
      acc0 = fmaf(a, f.x, acc0); acc1 = fmaf(a, f.y, acc1);
    }
    float o0 = (acc0 > 0.f) ? acc0 : expm1f(acc0);
    float o1 = (acc1 > 0.f) ? acc1 : expm1f(acc1);
    g_h[(size_t)node*64 + 2*lane]     = o0;
    g_h[(size_t)node*64 + 2*lane + 1] = o1;
    g_fcat[(size_t)node*256 + layer*64 + 2*lane]     = o0;
    g_fcat[(size_t)node*256 + layer*64 + 2*lane + 1] = o1;
  }
}

// ---------------- final 64 -> 1 layer ----------------
__global__ void mlp2_k(const float* __restrict__ T, const float* __restrict__ W2,
                       const float* __restrict__ b2, float* __restrict__ out, int n){
  int tid = threadIdx.x, lane = tid & 31, warp = tid >> 5;
  int row = blockIdx.x * 8 + warp;
  if (row >= n) return;
  float s = T[(size_t)row*64 + lane]*W2[lane] + T[(size_t)row*64 + 32 + lane]*W2[lane+32];
  #pragma unroll
  for (int o = 16; o; o >>= 1) s += __shfl_xor_sync(0xffffffffu, s, o);
  if (lane == 0) out[row] = fmaxf(s + b2[0], 0.f);
}

// ---------------- launch ----------------
extern "C" void kernel_launch(void* const* d_in, const int* in_sizes, int n_in,
                              void* d_out, int out_size)
{
  const float* x       = (const float*)d_in[0];
  const int*   esrc    = (const int*)  d_in[1];
  const int*   edst    = (const int*)  d_in[2];
  const float* W_embed = (const float*)d_in[3];
  const float* W_gat   = (const float*)d_in[4];
  const float* a_l     = (const float*)d_in[5];
  const float* a_r     = (const float*)d_in[6];
  const float* W0      = (const float*)d_in[7];
  const float* b0      = (const float*)d_in[8];
  const float* W1      = (const float*)d_in[9];
  const float* b1      = (const float*)d_in[10];
  const float* W2      = (const float*)d_in[11];
  const float* b2      = (const float*)d_in[12];
  float* out = (float*)d_out;

  int n = in_sizes[0] / 128;
  int e = in_sizes[1];

  float *h_ptr, *feat_ptr, *fcat_ptr;
  cudaGetSymbolAddress((void**)&h_ptr,    g_h);
  cudaGetSymbolAddress((void**)&feat_ptr, g_feat);
  cudaGetSymbolAddress((void**)&fcat_ptr, g_fcat);

  int tiles = (n + 127) / 128;
  int gW = (n + 7) / 8;

  // CSR build
  zero_deg_k<<<(n + 255)/256, 256>>>(n);
  hist_k<<<((e+3)/4 + 255)/256, 256>>>(edst, e);
  scan1_k<<<SCAN_BLOCKS, 256>>>(n);
  scan2_k<<<1, SCAN_BLOCKS>>>();
  scan3_k<<<SCAN_BLOCKS, 256>>>(n, e);
  scatter_k<<<((e+3)/4 + 255)/256, 256>>>(esrc, edst, e);

  // embed
  gemm2_k<128, 1><<<tiles, 256>>>(x, W_embed, nullptr, h_ptr, n);

  for (int l = 0; l < 4; ++l) {
    gemm2_k<64, 0><<<tiles, 256>>>(h_ptr, W_gat + l*64*64, nullptr, feat_ptr, n);
    eler_k<<<gW, 256>>>(a_l + l*64, a_r + l*64, n);
    agg_k<<<gW, 256>>>(n, l);
  }

  // MLP head
  gemm2_k<256, 2><<<tiles, 256>>>(fcat_ptr, W0, b0, feat_ptr, n);
  gemm2_k<64,  2><<<tiles, 256>>>(feat_ptr, W1, b1, h_ptr, n);
  mlp2_k<<<gW, 256>>>(h_ptr, W2, b2, out, n);
}